// round 11
// baseline (speedup 1.0000x reference)
#include <cuda_runtime.h>
#include <cuda_bf16.h>

// A = 8160 (68x120,s=8) + 2040 (34x60,s=16) + 510 (17x30,s=32) = 10710
// Output: [decoded B*A*16][fg B*A][ibc B*G*A], all f32.
//
// Separable masks: in_box(a,g) = xtest(col) & ytest(row). 50-bit tables per
// column/row; per anchor = 64-bit ANDs. Mask blocks stage per-anchor "both"
// bitmasks in shared; expansion assigns each thread ONE 4-anchor quad and a
// half of the g-range, loading the quad's mask words once and streaming 25
// g-rows with wide coalesced stores.

#define A_TOTAL 10710
#define A_L0    8160
#define A_L01   10200
#define NB      32
#define NG      50
#define NCH     16

#define NCOLS   210
#define NROWS   119

#define MASK_PER_BLK 512
#define MASK_ABLKS   ((A_TOTAL + MASK_PER_BLK - 1) / MASK_PER_BLK)  // 21
#define MASK_BLOCKS  (MASK_ABLKS * NB)        // 672
#define TOTF4        (NB * A_TOTAL * 4)       // 1370880
#define COPY_BLOCKS  ((TOTF4 + 511) / 512)    // 2678

__device__ __forceinline__ float bit2f(unsigned int word, int g) {
    // ((word >> g) & 1) * 1.0f  via sign-extend trick: 3 ALU ops
    const unsigned int m = (unsigned int)(((int)(word << (31 - g))) >> 31);
    return __uint_as_float(m & 0x3f800000u);
}

__device__ __forceinline__ void anchor_geom(int a, int& L, int& row, int& col) {
    int i, w;
    if (a < A_L0)       { L = 0; i = a;          w = 120; }
    else if (a < A_L01) { L = 1; i = a - A_L0;   w = 60;  }
    else                { L = 2; i = a - A_L01;  w = 30;  }
    row = i / w;
    col = i - row * w;
}

// global row index 0..118 (monotone in a)
__device__ __forceinline__ int grow_of(int a) {
    if (a < A_L0)   return a / 120;
    if (a < A_L01)  return 68 + (a - A_L0) / 60;
    return 102 + (a - A_L01) / 30;
}

__global__ __launch_bounds__(256)
void main_kernel(const float* __restrict__ preds,
                 const float* __restrict__ labels,
                 float* __restrict__ out) {
    __shared__ float4 sbox[NG];
    __shared__ float4 sctr[3][NG];
    __shared__ ulonglong2 sx[NCOLS];          // .x = box bits, .y = ctr bits
    __shared__ ulonglong2 sy[NROWS];
    __shared__ unsigned int slo[MASK_PER_BLK];   // both bits [0,32)
    __shared__ unsigned int shi[MASK_PER_BLK];   // both bits [32,50)

    const int blk = blockIdx.x;
    const int tid = threadIdx.x;

    if (blk >= MASK_BLOCKS) {
        // ============ copy/decode role: coalesced float4 streaming ==========
        const int cb = blk - MASK_BLOCKS;
        const float4* __restrict__ p4 = reinterpret_cast<const float4*>(preds);
        float4* __restrict__ o4 = reinterpret_cast<float4*>(out);
#pragma unroll
        for (int it = 0; it < 2; ++it) {
            const int j = cb * 512 + it * 256 + tid;
            if (j >= TOTF4) break;
            float4 v = p4[j];
            if ((j & 3) == 0) {                 // channels 0..3 of some anchor
                const int alin = j >> 2;
                const int b = alin / A_TOTAL;
                const int a = alin - b * A_TOTAL;
                int L, row, col;
                anchor_geom(a, L, row, col);
                const float s = (L == 0) ? 8.0f : (L == 1) ? 16.0f : 32.0f;
                float4 r;
                r.x = (v.x + (float)col) * s;
                r.y = (v.y + (float)row) * s;
                r.z = __expf(v.z) * s;
                r.w = __expf(v.w) * s;
                v = r;
            }
            o4[j] = v;
        }
        return;
    }

    // ======================= mask role ======================================
    const int b     = blk / MASK_ABLKS;
    const int abase = (blk % MASK_ABLKS) * MASK_PER_BLK;
    const int nA    = min(MASK_PER_BLK, A_TOTAL - abase);
    const int alast = abase + nA - 1;

    const float PINF = __int_as_float(0x7f800000);
    const float NINF = __int_as_float(0xff800000);

    // Phase 1: label bounds into shared
    if (tid < 3 * NG) {
        const int L = tid / NG;
        const int g = tid % NG;
        const float* lb = labels + ((size_t)b * NG + g) * 5;
        const float c  = lb[0];
        const float gx = lb[1];
        const float gy = lb[2];
        const float gw = lb[3];
        const float gh = lb[4];
        const bool valid = (c + gx + gy + gw + gh) > 0.0f;  // invalid rows are exactly 0
        if (L == 0) {
            const float hw = 0.5f * gw, hh = 0.5f * gh;
            sbox[g] = valid ? make_float4(gx - hw, gx + hw, gy - hh, gy + hh)
                            : make_float4(PINF, NINF, PINF, NINF);
        }
        const float r = (L == 0) ? 20.0f : (L == 1) ? 40.0f : 80.0f;  // 2.5*stride
        sctr[L][g] = valid ? make_float4(gx - r, gx + r, gy - r, gy + r)
                           : make_float4(PINF, NINF, PINF, NINF);
    }
    __syncthreads();

    // Phase 2: build ONLY the table entries this block touches (<=193, 1 pass)
    {
        const int Llo = (abase < A_L0) ? 0 : (abase < A_L01) ? 1 : 2;
        const int Lhi = (alast < A_L0) ? 0 : (alast < A_L01) ? 1 : 2;
        const int col_lo = (Llo == 0) ? 0 : (Llo == 1) ? 120 : 180;
        const int col_hi = (Lhi == 0) ? 119 : (Lhi == 1) ? 179 : 209;
        const int row_lo = grow_of(abase);
        const int row_hi = grow_of(alast);
        const int ncols = col_hi - col_lo + 1;
        const int nrows = row_hi - row_lo + 1;     // ncols + nrows <= 193 < 256

        if (tid < ncols) {
            const int gc = col_lo + tid;
            int L, col; float s;
            if (gc < 120)      { L = 0; col = gc;        s = 8.0f;  }
            else if (gc < 180) { L = 1; col = gc - 120;  s = 16.0f; }
            else               { L = 2; col = gc - 180;  s = 32.0f; }
            const float xc = ((float)col + 0.5f) * s;
            unsigned long long bb = 0ull, cc = 0ull;
#pragma unroll
            for (int g = 0; g < NG; ++g) {
                const float4 B = sbox[g];
                const float4 C = sctr[L][g];
                if (fminf(xc - B.x, B.y - xc) > 0.0f) bb |= (1ull << g);
                if (fminf(xc - C.x, C.y - xc) > 0.0f) cc |= (1ull << g);
            }
            sx[gc] = make_ulonglong2(bb, cc);
        } else if (tid < ncols + nrows) {
            const int gr = row_lo + (tid - ncols);
            int L, row; float s;
            if (gr < 68)       { L = 0; row = gr;       s = 8.0f;  }
            else if (gr < 102) { L = 1; row = gr - 68;  s = 16.0f; }
            else               { L = 2; row = gr - 102; s = 32.0f; }
            const float yc = ((float)row + 0.5f) * s;
            unsigned long long bb = 0ull, cc = 0ull;
#pragma unroll
            for (int g = 0; g < NG; ++g) {
                const float4 B = sbox[g];
                const float4 C = sctr[L][g];
                if (fminf(yc - B.z, B.w - yc) > 0.0f) bb |= (1ull << g);
                if (fminf(yc - C.z, C.w - yc) > 0.0f) cc |= (1ull << g);
            }
            sy[gr] = make_ulonglong2(bb, cc);
        }
    }
    __syncthreads();

    float* out_fg  = out + (size_t)NB * A_TOTAL * NCH;
    float* out_ibc = out_fg + (size_t)NB * A_TOTAL;

    // Phase 3a: both-bitmasks for 2 anchors/thread into shared; fg direct.
    {
        const int a0 = abase + tid * 2;
        if (a0 < A_TOTAL) {
            float fg2[2] = {0.0f, 0.0f};
#pragma unroll
            for (int i = 0; i < 2; ++i) {
                const int a = a0 + i;
                if (a >= A_TOTAL) break;
                int L, row, col;
                anchor_geom(a, L, row, col);
                const int gc = ((L == 0) ? 0 : (L == 1) ? 120 : 180) + col;
                const int gr = ((L == 0) ? 0 : (L == 1) ? 68  : 102) + row;
                const ulonglong2 xe = sx[gc];
                const ulonglong2 ye = sy[gr];
                const unsigned long long box = xe.x & ye.x;
                const unsigned long long ctr = xe.y & ye.y;
                const unsigned long long both = box & ctr;
                slo[tid * 2 + i] = (unsigned int)both;
                shi[tid * 2 + i] = (unsigned int)(both >> 32);
                // fg = any(box|ctr); "& fg" on ibc redundant (both!=0 => fg)
                fg2[i] = ((box | ctr) != 0ull) ? 1.0f : 0.0f;
            }
            float* pf = out_fg + (size_t)b * A_TOTAL + a0;   // even -> 8B aligned
            if (a0 + 1 < A_TOTAL)
                *reinterpret_cast<float2*>(pf) = make_float2(fg2[0], fg2[1]);
            else
                pf[0] = fg2[0];
        }
    }
    __syncthreads();

    // Phase 3b: thread owns quad q = tid&127 and half = tid>>7 (25 g-rows).
    // Loads the quad's mask words ONCE, then streams 25 g-rows.
    // Warp = 32 consecutive quads, same half -> 128 contiguous floats/store-row.
    {
        const int q    = tid & 127;
        const int half = tid >> 7;               // warp-uniform
        const int nquads = (nA + 3) >> 2;        // 128, or 118 in tail block
        if (q < nquads) {
            const uint4 wlo = *reinterpret_cast<const uint4*>(&slo[q * 4]);
            const uint4 whi = *reinterpret_cast<const uint4*>(&shi[q * 4]);
            float* p = out_ibc + (size_t)b * NG * A_TOTAL + abase + q * 4
                     + (size_t)(half * 25) * A_TOTAL;
            const int rem = nA - q * 4;          // >=1
            const bool full = (rem >= 4);
#pragma unroll
            for (int it = 0; it < 25; ++it) {
                // g = half*25 + it; source word + bit position:
                uint4 w; int gs;
                if (half == 0)      { w = wlo; gs = it; }          // g in [0,25)
                else if (it < 7)    { w = wlo; gs = 25 + it; }     // g in [25,32)
                else                { w = whi; gs = it - 7; }      // g in [32,50)
                const float f0 = bit2f(w.x, gs);
                const float f1 = bit2f(w.y, gs);
                const float f2 = bit2f(w.z, gs);
                const float f3 = bit2f(w.w, gs);
                if (full) {
                    if (((half + it) & 1) == 0) {
                        // even g: b*NG*A, abase, q*4 all %4==0 and g*A %4==0 -> 16B
                        *reinterpret_cast<float4*>(p) = make_float4(f0, f1, f2, f3);
                    } else {
                        reinterpret_cast<float2*>(p)[0] = make_float2(f0, f1);
                        reinterpret_cast<float2*>(p)[1] = make_float2(f2, f3);
                    }
                } else {                          // partial quad (tail block)
                    p[0] = f0;
                    if (rem > 1) p[1] = f1;
                    if (rem > 2) p[2] = f2;
                }
                p += A_TOTAL;
            }
        }
    }
}

extern "C" void kernel_launch(void* const* d_in, const int* in_sizes, int n_in,
                              void* d_out, int out_size) {
    const float* preds  = (const float*)d_in[0];
    const float* labels = (const float*)d_in[1];
    float* out = (float*)d_out;

    main_kernel<<<MASK_BLOCKS + COPY_BLOCKS, 256>>>(preds, labels, out);
}